// round 3
// baseline (speedup 1.0000x reference)
#include <cuda_runtime.h>
#include <cuda_bf16.h>
#include <math.h>

#define SEQ   2048
#define NH    16
#define DQK   576
#define DV    512
#define NTOP  1024
#define SCALE 0.08838834764831845f

__device__ __align__(16) float g_q   [SEQ * NH * DQK];
__device__ __align__(16) float g_kv  [SEQ * DQK];
__device__ __align__(16) float g_ql  [SEQ * NH * 128];
__device__ __align__(16) float g_iq  [SEQ * NH * 128];
__device__ __align__(16) float g_ik  [SEQ * 128];
__device__ __align__(16) float g_ckv [SEQ * 128];
__device__ __align__(16) float g_w   [SEQ * NH];
__device__ __align__(16) float g_kbT [NH * 512 * 128];
__device__ __align__(16) int   g_sel [SEQ * NTOP];
__device__               int   g_nsel[SEQ];
__device__ __align__(16) float g_attn[SEQ * NH * DV];

__device__ __forceinline__ float dot4(float4 a, float4 b) {
    return a.x*b.x + a.y*b.y + a.z*b.z + a.w*b.w;
}
__device__ __forceinline__ void axpy4(float4& o, float a, float4 b) {
    o.x += a*b.x; o.y += a*b.y; o.z += a*b.z; o.w += a*b.w;
}
__device__ __forceinline__ void scl4(float4& o, float c) { o.x*=c; o.y*=c; o.z*=c; o.w*=c; }

// NT SGEMM: C[m,n] = sum_k A[m,k]B[n,k]; 128x128 tile, BK=8, 8x8/thread.
// M multiple of 128; K multiple of 8. Batched over blockIdx.z.
__global__ __launch_bounds__(256, 2)
void sgemm_nt(const float* __restrict__ A, const float* __restrict__ B,
              float* __restrict__ C, int N, int K, int lda, int ldb, int ldc,
              long long sA, long long sB, long long sC,
              const float* __restrict__ bias, int do_abs)
{
    A += (long long)blockIdx.z * sA;
    B += (long long)blockIdx.z * sB;
    C += (long long)blockIdx.z * sC;
    __shared__ float As[8][128], Bs[8][128];
    const int tid = threadIdx.x, bm = blockIdx.y*128, bn = blockIdx.x*128;
    const int arow = tid >> 1, acol = (tid & 1) << 2;
    const int tm = (tid >> 4) << 3, tn = (tid & 15) << 3;
    float acc[8][8];
#pragma unroll
    for (int i = 0; i < 8; i++)
#pragma unroll
        for (int j = 0; j < 8; j++) acc[i][j] = 0.f;

    for (int k0 = 0; k0 < K; k0 += 8) {
        float4 av = *(const float4*)(A + (bm + arow) * lda + k0 + acol);
        float4 bv = make_float4(0.f,0.f,0.f,0.f);
        if (bn + arow < N) bv = *(const float4*)(B + (bn + arow) * ldb + k0 + acol);
        As[acol+0][arow]=av.x; As[acol+1][arow]=av.y; As[acol+2][arow]=av.z; As[acol+3][arow]=av.w;
        Bs[acol+0][arow]=bv.x; Bs[acol+1][arow]=bv.y; Bs[acol+2][arow]=bv.z; Bs[acol+3][arow]=bv.w;
        __syncthreads();
#pragma unroll
        for (int kk = 0; kk < 8; kk++) {
            float4 a0=*(const float4*)&As[kk][tm], a1=*(const float4*)&As[kk][tm+4];
            float4 b0=*(const float4*)&Bs[kk][tn], b1=*(const float4*)&Bs[kk][tn+4];
            float a[8]={a0.x,a0.y,a0.z,a0.w,a1.x,a1.y,a1.z,a1.w};
            float b[8]={b0.x,b0.y,b0.z,b0.w,b1.x,b1.y,b1.z,b1.w};
#pragma unroll
            for (int i = 0; i < 8; i++)
#pragma unroll
                for (int j = 0; j < 8; j++) acc[i][j] += a[i]*b[j];
        }
        __syncthreads();
    }
#pragma unroll
    for (int i = 0; i < 8; i++) {
        int row = bm + tm + i;
#pragma unroll
        for (int j = 0; j < 8; j++) {
            int col = bn + tn + j;
            if (col < N) {
                float v = acc[i][j];
                if (bias)   v += bias[col];
                if (do_abs) v  = fabsf(v);
                C[row * ldc + col] = v;
            }
        }
    }
}

__global__ void transpose_kb(const float* __restrict__ kvb) {
    int idx = blockIdx.x*256 + threadIdx.x;            // 16*512*128
    int h = idx >> 16, r = (idx >> 7) & 511, d = idx & 127;
    g_kbT[idx] = kvb[((h << 8) + d) * 512 + r];
}
__global__ void build_kv(const float* __restrict__ kp, const float* __restrict__ kr) {
    int idx = blockIdx.x*256 + threadIdx.x;            // 2048*576
    int s = idx / 576, r = idx - s*576;
    g_kv[idx] = (r < 512) ? kp[s*512 + r] : kr[s*64 + (r - 512)];
}
__global__ void build_qrot(const float* __restrict__ qr) {
    int idx = blockIdx.x*256 + threadIdx.x;            // 2048*16*64
    int s = idx >> 10, rem = idx & 1023, h = rem >> 6, i = rem & 63;
    g_q[s*(NH*DQK) + h*DQK + 512 + i] = qr[(h*SEQ + s)*64 + i];
}
__global__ void build_ik(const float* __restrict__ cosb, const float* __restrict__ sinb,
                         const float* __restrict__ knorm) {
    int s = blockIdx.x, t = threadIdx.x;               // 64 threads
    float pv = g_ckv[s*128 + 64 + t];
    float ss = pv * pv;
#pragma unroll
    for (int o = 16; o; o >>= 1) ss += __shfl_xor_sync(0xffffffffu, ss, o);
    __shared__ float red[2];
    if ((t & 31) == 0) red[t >> 5] = ss;
    __syncthreads();
    float inv = rsqrtf((red[0] + red[1]) * (1.f/64.f) + 1e-6f);
    g_ik[s*128 + 64 + t] = pv * inv * knorm[t];
    if (t < 32) {
        float x0 = g_ckv[s*128 + 2*t], x1 = g_ckv[s*128 + 2*t + 1];
        g_ik[s*128 + t]      = x0*cosb[s*64 + t]      - x1*sinb[s*64 + t];
        g_ik[s*128 + 32 + t] = x1*cosb[s*64 + 32 + t] + x0*sinb[s*64 + 32 + t];
    }
}
__global__ void rope_iq(const float* __restrict__ cosb, const float* __restrict__ sinb) {
    int idx = blockIdx.x*256 + threadIdx.x;            // 2048*16*32
    int s = idx >> 9, rem = idx & 511, h = rem >> 5, i = rem & 31;
    int base = s*(NH*128) + h*128;
    float x0 = g_ql[base + 2*i], x1 = g_ql[base + 2*i + 1];
    g_iq[base + i]      = x0*cosb[s*64 + i]      - x1*sinb[s*64 + i];
    g_iq[base + 32 + i] = x1*cosb[s*64 + 32 + i] + x0*sinb[s*64 + 32 + i];
    g_iq[base + 64 + i] = g_ql[base + 64 + i];
    g_iq[base + 96 + i] = g_ql[base + 96 + i];
}

// scores + exact top-1024 (ties -> lowest index, matching jax.lax.top_k)
__global__ __launch_bounds__(256)
void indexer_kernel()
{
    const int qi = blockIdx.x, t = threadIdx.x;
    if (qi < NTOP) {                                    // all causal keys selected
        for (int k = t; k <= qi; k += 256) g_sel[qi*NTOP + k] = k;
        if (t == 0) g_nsel[qi] = qi + 1;
        return;
    }
    __shared__ float4 iq4[16*33];
    __shared__ float4 ik4[32*33];
    __shared__ float  ssc[SEQ];
    __shared__ float  wsh[16];
    __shared__ unsigned int hist[256];
    __shared__ unsigned long long s_prefix;
    __shared__ unsigned int s_kneed, s_cnt;

    const float4* iqg = (const float4*)g_iq + qi * 512;
#pragma unroll
    for (int u = 0; u < 2; u++) {
        int f = t + 256*u;
        iq4[(f >> 5)*33 + (f & 31)] = iqg[f];
    }
    if (t < 16) wsh[t] = g_w[qi*16 + t];
    if (t == 0) { s_prefix = 0ULL; s_kneed = NTOP; s_cnt = 0; }
    __syncthreads();

    const int n = qi + 1;
    const int row = t >> 3, cb = t & 7;                 // 32 keys/tile, 8 thr/key
    for (int k0 = 0; k0 < n; k0 += 32) {
        int k = k0 + row;
        float4* dst = &ik4[row*33];
        if (k < n) {
            const float4* src = (const float4*)g_ik + k*32;
#pragma unroll
            for (int u = 0; u < 4; u++) dst[cb + 8*u] = src[cb + 8*u];
        } else {
            float4 z = make_float4(0.f,0.f,0.f,0.f);
#pragma unroll
            for (int u = 0; u < 4; u++) dst[cb + 8*u] = z;
        }
        __syncthreads();
        const float4* ap0 = &iq4[(cb*2)*33];
        const float4* ap1 = &iq4[(cb*2 + 1)*33];
        const float4* bp  = &ik4[row*33];
        float a0 = 0.f, a1 = 0.f;
#pragma unroll
        for (int dc = 0; dc < 32; dc++) {
            float4 bv = bp[dc];
            a0 += dot4(ap0[dc], bv);
            a1 += dot4(ap1[dc], bv);
        }
        float part = wsh[cb*2]*fmaxf(a0*SCALE, 0.f) + wsh[cb*2+1]*fmaxf(a1*SCALE, 0.f);
        part += __shfl_xor_sync(0xffffffffu, part, 1);
        part += __shfl_xor_sync(0xffffffffu, part, 2);
        part += __shfl_xor_sync(0xffffffffu, part, 4);
        if (cb == 0 && k < n) ssc[k] = part;
        __syncthreads();
    }

    for (int pass = 5; pass >= 0; pass--) {             // radix select, 43-bit keys
        const int shift = pass * 8;
        hist[t] = 0u;
        __syncthreads();
        unsigned long long pref = s_prefix;
        for (int k = t; k < n; k += 256) {
            unsigned long long key =
                (((unsigned long long)__float_as_uint(ssc[k])) << 11) | (unsigned)(2047 - k);
            if ((key >> (shift + 8)) == (pref >> (shift + 8)))
                atomicAdd(&hist[(unsigned)(key >> shift) & 255u], 1u);
        }
        __syncthreads();
        if (t == 0) {
            unsigned c = 0;
            for (int d = 255; d >= 0; d--) {
                unsigned c2 = c + hist[d];
                if (c2 >= s_kneed) {
                    s_prefix |= ((unsigned long long)d) << shift;
                    s_kneed  -= c;
                    break;
                }
                c = c2;
            }
        }
        __syncthreads();
    }
    const unsigned long long T = s_prefix;
    for (int k = t; k < n; k += 256) {
        unsigned long long key =
            (((unsigned long long)__float_as_uint(ssc[k])) << 11) | (unsigned)(2047 - k);
        if (key >= T) g_sel[qi*NTOP + atomicAdd(&s_cnt, 1u)] = k;
    }
    if (t == 0) g_nsel[qi] = NTOP;
}

// sparse attention: block/query, 8 warps x 2 heads, 16-key smem tiles,
// online softmax, fused attn@V over kv[:,:512]
#define KTILE 16
__global__ __launch_bounds__(256)
void attn_kernel()
{
    __shared__ float4 kvs[KTILE * 144];                 // 36,864 B
    const int qi = blockIdx.x, t = threadIdx.x;
    const int w = t >> 5, lane = t & 31;
    const int h0 = w*2, h1 = h0 + 1;
    const bool half = lane < 16;

    const float4* q4 = (const float4*)g_q + (long long)qi * (NH*DQK/4);
    float4 z = make_float4(0.f,0.f,0.f,0.f);
    float4 qa[5], qb[5];
#pragma unroll
    for (int u = 0; u < 4; u++) {
        qa[u] = q4[h0*144 + lane + 32*u];
        qb[u] = q4[h1*144 + lane + 32*u];
    }
    qa[4] = z; qb[4] = z;
    if (half) { qa[4] = q4[h0*144 + 128 + lane]; qb[4] = q4[h1*144 + 128 + lane]; }

    float m0 = -1e30f, l0 = 0.f, m1 = -1e30f, l1 = 0.f;
    float4 o0[4], o1[4];
#pragma unroll
    for (int u = 0; u < 4; u++) { o0[u] = z; o1[u] = z; }

    const int n = g_nsel[qi];
    const int* lst = g_sel + qi*NTOP;

    for (int base = 0; base < n; base += KTILE) {
        int tk = n - base; if (tk > KTILE) tk = KTILE;
#pragma unroll
        for (int rr = 0; rr < 2; rr++) {
            int r = w*2 + rr;
            if (r < tk) {
                int key = __ldg(&lst[base + r]);
                const float4* src = (const float4*)g_kv + key*144;
                float4* dst = kvs + r*144;
                dst[lane]      = src[lane];
                dst[lane + 32] = src[lane + 32];
                dst[lane + 64] = src[lane + 64];
                dst[lane + 96] = src[lane + 96];
                if (half) dst[128 + lane] = src[128 + lane];
            }
        }
        __syncthreads();
        for (int j = 0; j < tk; j++) {
            const float4* kr = kvs + j*144;
            float4 b0 = kr[lane], b1 = kr[lane+32], b2 = kr[lane+64], b3 = kr[lane+96];
            float sA = dot4(qa[0],b0)+dot4(qa[1],b1)+dot4(qa[2],b2)+dot4(qa[3],b3);
            float sB = dot4(qb[0],b0)+dot4(qb[1],b1)+dot4(qb[2],b2)+dot4(qb[3],b3);
            if (half) {
                float4 bt = kr[128 + lane];
                sA += dot4(qa[4], bt);
                sB += dot4(qb[4], bt);
            }
#pragma unroll
            for (int o = 16; o; o >>= 1) {
                sA += __shfl_xor_sync(0xffffffffu, sA, o);
                sB += __shfl_xor_sync(0xffffffffu, sB, o);
            }
            float lg0 = sA * SCALE, lg1 = sB * SCALE;
            if (lg0 > m0) {
                float c = __expf(m0 - lg0); l0 *= c;
#pragma unroll
                for (int u = 0; u < 4; u++) scl4(o0[u], c);
                m0 = lg0;
            }
            float p0 = __expf(lg0 - m0); l0 += p0;
            axpy4(o0[0],p0,b0); axpy4(o0[1],p0,b1); axpy4(o0[2],p0,b2); axpy4(o0[3],p0,b3);
            if (lg1 > m1) {
                float c = __expf(m1 - lg1); l1 *= c;
#pragma unroll
                for (int u = 0; u < 4; u++) scl4(o1[u], c);
                m1 = lg1;
            }
            float p1 = __expf(lg1 - m1); l1 += p1;
            axpy4(o1[0],p1,b0); axpy4(o1[1],p1,b1); axpy4(o1[2],p1,b2); axpy4(o1[3],p1,b3);
        }
        __syncthreads();
    }
    float i0 = 1.f/l0, i1 = 1.f/l1;
    float4* ao = (float4*)g_attn + (long long)qi * (NH*DV/4);
#pragma unroll
    for (int u = 0; u < 4; u++) {
        float4 v = o0[u]; scl4(v, i0); ao[h0*128 + lane + 32*u] = v;
        float4 v2 = o1[u]; scl4(v2, i1); ao[h1*128 + lane + 32*u] = v2;
    }
}

template <typename T> static T* sym(const void* s) {
    void* p = nullptr; cudaGetSymbolAddress(&p, s); return (T*)p;
}

extern "C" void kernel_launch(void* const* d_in, const int* in_sizes, int n_in,
                              void* d_out, int out_size)
{
    (void)in_sizes; (void)n_in; (void)out_size;
    const float* q_latent = (const float*)d_in[0];
    const float* hidden   = (const float*)d_in[1];
    const float* cosb     = (const float*)d_in[2];
    const float* sinb     = (const float*)d_in[3];
    const float* q_pass   = (const float*)d_in[4];
    const float* q_rot    = (const float*)d_in[5];
    const float* k_pass   = (const float*)d_in[6];
    const float* k_rot    = (const float*)d_in[7];
    const float* kvb      = (const float*)d_in[9];
    const float* wqb      = (const float*)d_in[10];
    const float* wkw      = (const float*)d_in[11];
    const float* knorm    = (const float*)d_in[12];
    const float* wpw      = (const float*)d_in[13];
    const float* wpb      = (const float*)d_in[14];
    float* out = (float*)d_out;

    float* p_q    = sym<float>(g_q);
    float* p_ql   = sym<float>(g_ql);
    float* p_ckv  = sym<float>(g_ckv);
    float* p_w    = sym<float>(g_w);
    float* p_kbT  = sym<float>(g_kbT);
    float* p_attn = sym<float>(g_attn);

    transpose_kb<<<4096, 256>>>(kvb);
    // ql = q_latent @ wq_b^T   (2048x2048, K=1536)
    sgemm_nt<<<dim3(16,16,1), 256>>>(q_latent, wqb, p_ql, 2048, 1536,
                                     1536, 1536, 2048, 0, 0, 0, nullptr, 0);
    // ckv = hidden @ wk^T      (2048x128, K=2048)
    sgemm_nt<<<dim3(1,16,1), 256>>>(hidden, wkw, p_ckv, 128, 2048,
                                    2048, 2048, 128, 0, 0, 0, nullptr, 0);
    // w = |hidden @ wproj^T + b|  (2048x16)
    sgemm_nt<<<dim3(1,16,1), 256>>>(hidden, wpw, p_w, 16, 2048,
                                    2048, 2048, 16, 0, 0, 0, wpb, 1);
    // q_abs[h]: q_pass[h] @ k_b[h]^T -> q[s][h][0:512]
    sgemm_nt<<<dim3(4,16,16), 256>>>(q_pass, p_kbT, p_q, 512, 128,
                                     128, 128, NH*DQK,
                                     (long long)SEQ*128, 512LL*128, DQK, nullptr, 0);
    build_kv  <<<4608, 256>>>(k_pass, k_rot);
    build_qrot<<<8192, 256>>>(q_rot);
    build_ik  <<<SEQ, 64>>>(cosb, sinb, knorm);
    rope_iq   <<<4096, 256>>>(cosb, sinb);

    indexer_kernel<<<SEQ, 256>>>();
    attn_kernel<<<SEQ, 256>>>();

    // out[s,h,d] = sum_r attn[s,h,r] * v_b[h,d,r]
    sgemm_nt<<<dim3(1,16,16), 256>>>(p_attn, kvb + 128*512, out, 128, 512,
                                     NH*DV, 512, NH*128,
                                     512LL, 256LL*512, 128LL, nullptr, 0);
}

// round 4
// speedup vs baseline: 1.1626x; 1.1626x over previous
#include <cuda_runtime.h>
#include <cuda_bf16.h>
#include <math.h>

#define SEQ   2048
#define NH    16
#define DQK   576
#define DV    512
#define NTOP  1024
#define SCALE 0.08838834764831845f

typedef unsigned long long u64;

__device__ __align__(16) float g_q    [SEQ * NH * DQK];
__device__ __align__(16) float g_kv   [SEQ * DQK];
__device__ __align__(16) float g_ql   [SEQ * NH * 128];
__device__ __align__(16) float g_iq   [SEQ * NH * 128];
__device__ __align__(16) float g_ik   [SEQ * 128];
__device__ __align__(16) float g_ckv  [SEQ * 128];
__device__ __align__(16) float g_w    [SEQ * NH];
__device__ __align__(16) float g_part [8 * SEQ * 128];
__device__ __align__(16) float g_partw[8 * SEQ * 16];
__device__ __align__(16) int   g_sel  [SEQ * NTOP];
__device__               int   g_nsel [SEQ];
__device__ __align__(16) float g_attn [SEQ * NH * DV];

// ---- packed f32x2 helpers (sm_103a) ----
__device__ __forceinline__ u64 pk2(float lo, float hi) {
    u64 r; asm("mov.b64 %0,{%1,%2};" : "=l"(r) : "f"(lo), "f"(hi)); return r;
}
__device__ __forceinline__ u64 pkdup(float x) { return pk2(x, x); }
__device__ __forceinline__ void upk(u64 v, float& lo, float& hi) {
    asm("mov.b64 {%0,%1},%2;" : "=f"(lo), "=f"(hi) : "l"(v));
}
__device__ __forceinline__ u64 fma2(u64 a, u64 b, u64 c) {
    u64 d; asm("fma.rn.f32x2 %0,%1,%2,%3;" : "=l"(d) : "l"(a), "l"(b), "l"(c)); return d;
}
__device__ __forceinline__ u64 mul2(u64 a, u64 b) {
    u64 d; asm("mul.rn.f32x2 %0,%1,%2;" : "=l"(d) : "l"(a), "l"(b)); return d;
}
__device__ __forceinline__ u64 add2(u64 a, u64 b) {
    u64 d; asm("add.rn.f32x2 %0,%1,%2;" : "=l"(d) : "l"(a), "l"(b)); return d;
}
__device__ __forceinline__ float hsum2(u64 v) { float l, h; upk(v, l, h); return l + h; }

// NT SGEMM (or NN if transB): C[m,n]=sum_k A[m,k]*B[n,k] (or B[k,n]).
// 128x128 tile, BK=8, 8x8/thread via f32x2. Batched over blockIdx.z.
__global__ __launch_bounds__(256, 2)
void sgemm_nt(const float* __restrict__ A, const float* __restrict__ B,
              float* __restrict__ C, int N, int K, int lda, int ldb, int ldc,
              long long sA, long long sB, long long sC, int transB)
{
    A += (long long)blockIdx.z * sA;
    B += (long long)blockIdx.z * sB;
    C += (long long)blockIdx.z * sC;
    __shared__ float As[8][128], Bs[8][128];
    const int tid = threadIdx.x, bm = blockIdx.y*128, bn = blockIdx.x*128;
    const int arow = tid >> 1, acol = (tid & 1) << 2;
    const int bkk = tid >> 5, bnc = (tid & 31) << 2;
    const int tm = (tid >> 4) << 3, tn = (tid & 15) << 3;
    u64 acc[8][4];
#pragma unroll
    for (int i = 0; i < 8; i++)
#pragma unroll
        for (int p = 0; p < 4; p++) acc[i][p] = 0ULL;

    for (int k0 = 0; k0 < K; k0 += 8) {
        float4 av = *(const float4*)(A + (bm + arow) * lda + k0 + acol);
        As[acol+0][arow]=av.x; As[acol+1][arow]=av.y; As[acol+2][arow]=av.z; As[acol+3][arow]=av.w;
        if (!transB) {
            float4 bv = make_float4(0.f,0.f,0.f,0.f);
            if (bn + arow < N) bv = *(const float4*)(B + (bn + arow) * ldb + k0 + acol);
            Bs[acol+0][arow]=bv.x; Bs[acol+1][arow]=bv.y; Bs[acol+2][arow]=bv.z; Bs[acol+3][arow]=bv.w;
        } else {
            float4 bv = make_float4(0.f,0.f,0.f,0.f);
            if (bn + bnc < N) bv = *(const float4*)(B + (k0 + bkk) * ldb + bn + bnc);
            *(float4*)&Bs[bkk][bnc] = bv;
        }
        __syncthreads();
#pragma unroll
        for (int kk = 0; kk < 8; kk++) {
            float4 a0=*(const float4*)&As[kk][tm], a1=*(const float4*)&As[kk][tm+4];
            const u64* bp = (const u64*)&Bs[kk][tn];
            u64 b0=bp[0], b1=bp[1], b2=bp[2], b3=bp[3];
            float aarr[8] = {a0.x,a0.y,a0.z,a0.w,a1.x,a1.y,a1.z,a1.w};
#pragma unroll
            for (int i = 0; i < 8; i++) {
                u64 ai = pkdup(aarr[i]);
                acc[i][0]=fma2(ai,b0,acc[i][0]); acc[i][1]=fma2(ai,b1,acc[i][1]);
                acc[i][2]=fma2(ai,b2,acc[i][2]); acc[i][3]=fma2(ai,b3,acc[i][3]);
            }
        }
        __syncthreads();
    }
#pragma unroll
    for (int i = 0; i < 8; i++) {
        int row = bm + tm + i;
        float c[8];
#pragma unroll
        for (int p = 0; p < 4; p++) upk(acc[i][p], c[2*p], c[2*p+1]);
#pragma unroll
        for (int j = 0; j < 8; j++) {
            int col = bn + tn + j;
            if (col < N) C[row * ldc + col] = c[j];
        }
    }
}

__global__ void reduce_ckv() {
    int i = blockIdx.x*256 + threadIdx.x;               // 2048*128
    float s = 0.f;
#pragma unroll
    for (int z = 0; z < 8; z++) s += g_part[z*(SEQ*128) + i];
    g_ckv[i] = s;
}
__global__ void reduce_w(const float* __restrict__ bias) {
    int i = blockIdx.x*256 + threadIdx.x;               // 2048*16
    float s = 0.f;
#pragma unroll
    for (int z = 0; z < 8; z++) s += g_partw[z*(SEQ*16) + i];
    g_w[i] = fabsf(s + bias[i & 15]);
}

__global__ void build_kv(const float* __restrict__ kp, const float* __restrict__ kr) {
    int idx = blockIdx.x*256 + threadIdx.x;            // 2048*576
    int s = idx / 576, r = idx - s*576;
    g_kv[idx] = (r < 512) ? kp[s*512 + r] : kr[s*64 + (r - 512)];
}
__global__ void build_qrot(const float* __restrict__ qr) {
    int idx = blockIdx.x*256 + threadIdx.x;            // 2048*16*64
    int s = idx >> 10, rem = idx & 1023, h = rem >> 6, i = rem & 63;
    g_q[s*(NH*DQK) + h*DQK + 512 + i] = qr[(h*SEQ + s)*64 + i];
}
__global__ void build_ik(const float* __restrict__ cosb, const float* __restrict__ sinb,
                         const float* __restrict__ knorm) {
    int s = blockIdx.x, t = threadIdx.x;               // 64 threads
    float pv = g_ckv[s*128 + 64 + t];
    float ss = pv * pv;
#pragma unroll
    for (int o = 16; o; o >>= 1) ss += __shfl_xor_sync(0xffffffffu, ss, o);
    __shared__ float red[2];
    if ((t & 31) == 0) red[t >> 5] = ss;
    __syncthreads();
    float inv = rsqrtf((red[0] + red[1]) * (1.f/64.f) + 1e-6f);
    g_ik[s*128 + 64 + t] = pv * inv * knorm[t];
    if (t < 32) {
        float x0 = g_ckv[s*128 + 2*t], x1 = g_ckv[s*128 + 2*t + 1];
        g_ik[s*128 + t]      = x0*cosb[s*64 + t]      - x1*sinb[s*64 + t];
        g_ik[s*128 + 32 + t] = x1*cosb[s*64 + 32 + t] + x0*sinb[s*64 + 32 + t];
    }
}
__global__ void rope_iq(const float* __restrict__ cosb, const float* __restrict__ sinb) {
    int idx = blockIdx.x*256 + threadIdx.x;            // 2048*16*32
    int s = idx >> 9, rem = idx & 511, h = rem >> 5, i = rem & 31;
    int base = s*(NH*128) + h*128;
    float x0 = g_ql[base + 2*i], x1 = g_ql[base + 2*i + 1];
    g_iq[base + i]      = x0*cosb[s*64 + i]      - x1*sinb[s*64 + i];
    g_iq[base + 32 + i] = x1*cosb[s*64 + 32 + i] + x0*sinb[s*64 + 32 + i];
    g_iq[base + 64 + i] = g_ql[base + 64 + i];
    g_iq[base + 96 + i] = g_ql[base + 96 + i];
}

// scores + exact top-1024 (ties -> lowest index, matching jax.lax.top_k)
__global__ __launch_bounds__(256)
void indexer_kernel()
{
    const int qi = blockIdx.x, t = threadIdx.x;
    if (qi < NTOP) {
        for (int k = t; k <= qi; k += 256) g_sel[qi*NTOP + k] = k;
        if (t == 0) g_nsel[qi] = qi + 1;
        return;
    }
    __shared__ float4 iq4[16*33];
    __shared__ float4 ik4[32*33];
    __shared__ float  ssc[SEQ];
    __shared__ float  wsh[16];
    __shared__ unsigned int hist[256];
    __shared__ unsigned long long s_prefix;
    __shared__ unsigned int s_kneed, s_cnt;

    const float4* iqg = (const float4*)g_iq + qi * 512;
#pragma unroll
    for (int u = 0; u < 2; u++) {
        int f = t + 256*u;
        iq4[(f >> 5)*33 + (f & 31)] = iqg[f];
    }
    if (t < 16) wsh[t] = g_w[qi*16 + t];
    if (t == 0) { s_prefix = 0ULL; s_kneed = NTOP; s_cnt = 0; }
    __syncthreads();

    const int n = qi + 1;
    const int row = t >> 3, cb = t & 7;
    for (int k0 = 0; k0 < n; k0 += 32) {
        int k = k0 + row;
        float4* dst = &ik4[row*33];
        if (k < n) {
            const float4* src = (const float4*)g_ik + k*32;
#pragma unroll
            for (int u = 0; u < 4; u++) dst[cb + 8*u] = src[cb + 8*u];
        } else {
            float4 z = make_float4(0.f,0.f,0.f,0.f);
#pragma unroll
            for (int u = 0; u < 4; u++) dst[cb + 8*u] = z;
        }
        __syncthreads();
        const u64* ap0 = (const u64*)&iq4[(cb*2)*33];
        const u64* ap1 = (const u64*)&iq4[(cb*2 + 1)*33];
        const u64* bp  = (const u64*)&ik4[row*33];
        u64 a0a=0ULL, a0b=0ULL, a1a=0ULL, a1b=0ULL;
#pragma unroll
        for (int dc = 0; dc < 32; dc++) {
            u64 b0 = bp[2*dc], b1 = bp[2*dc+1];
            a0a = fma2(ap0[2*dc],   b0, a0a);
            a0b = fma2(ap0[2*dc+1], b1, a0b);
            a1a = fma2(ap1[2*dc],   b0, a1a);
            a1b = fma2(ap1[2*dc+1], b1, a1b);
        }
        float a0 = hsum2(add2(a0a, a0b));
        float a1 = hsum2(add2(a1a, a1b));
        float part = wsh[cb*2]*fmaxf(a0*SCALE, 0.f) + wsh[cb*2+1]*fmaxf(a1*SCALE, 0.f);
        part += __shfl_xor_sync(0xffffffffu, part, 1);
        part += __shfl_xor_sync(0xffffffffu, part, 2);
        part += __shfl_xor_sync(0xffffffffu, part, 4);
        if (cb == 0 && k < n) ssc[k] = part;
        __syncthreads();
    }

    for (int pass = 5; pass >= 0; pass--) {             // radix select, 43-bit keys
        const int shift = pass * 8;
        hist[t] = 0u;
        __syncthreads();
        unsigned long long pref = s_prefix;
        for (int k = t; k < n; k += 256) {
            unsigned long long key =
                (((unsigned long long)__float_as_uint(ssc[k])) << 11) | (unsigned)(2047 - k);
            if ((key >> (shift + 8)) == (pref >> (shift + 8)))
                atomicAdd(&hist[(unsigned)(key >> shift) & 255u], 1u);
        }
        __syncthreads();
        if (t == 0) {
            unsigned c = 0;
            for (int d = 255; d >= 0; d--) {
                unsigned c2 = c + hist[d];
                if (c2 >= s_kneed) {
                    s_prefix |= ((unsigned long long)d) << shift;
                    s_kneed  -= c;
                    break;
                }
                c = c2;
            }
        }
        __syncthreads();
    }
    const unsigned long long T = s_prefix;
    for (int k = t; k < n; k += 256) {
        unsigned long long key =
            (((unsigned long long)__float_as_uint(ssc[k])) << 11) | (unsigned)(2047 - k);
        if (key >= T) g_sel[qi*NTOP + atomicAdd(&s_cnt, 1u)] = k;
    }
    if (t == 0) g_nsel[qi] = NTOP;
}

// sparse attention: block/query, 8 warps x 2 heads, online softmax, f32x2 math
#define KTILE 16
__global__ __launch_bounds__(256, 2)
void attn_kernel()
{
    __shared__ float4 kvs[KTILE * 144];
    const int qi = blockIdx.x, t = threadIdx.x;
    const int w = t >> 5, lane = t & 31;
    const int h0 = w*2, h1 = h0 + 1;
    const bool half = lane < 16;

    const u64* q2 = (const u64*)g_q + (long long)qi * (NH*DQK/2);
    u64 qa[10], qb[10];
#pragma unroll
    for (int u = 0; u < 4; u++) {
        qa[2*u]   = q2[h0*288 + (lane+32*u)*2];
        qa[2*u+1] = q2[h0*288 + (lane+32*u)*2 + 1];
        qb[2*u]   = q2[h1*288 + (lane+32*u)*2];
        qb[2*u+1] = q2[h1*288 + (lane+32*u)*2 + 1];
    }
    qa[8]=qa[9]=qb[8]=qb[9]=0ULL;
    if (half) {
        qa[8] = q2[h0*288 + (128+lane)*2]; qa[9] = q2[h0*288 + (128+lane)*2 + 1];
        qb[8] = q2[h1*288 + (128+lane)*2]; qb[9] = q2[h1*288 + (128+lane)*2 + 1];
    }

    float m0 = -1e30f, l0 = 0.f, m1 = -1e30f, l1 = 0.f;
    u64 o0[8], o1[8];
#pragma unroll
    for (int p = 0; p < 8; p++) { o0[p] = 0ULL; o1[p] = 0ULL; }

    const int n = g_nsel[qi];
    const int* lst = g_sel + qi*NTOP;

    for (int base = 0; base < n; base += KTILE) {
        int tk = n - base; if (tk > KTILE) tk = KTILE;
#pragma unroll
        for (int rr = 0; rr < 2; rr++) {
            int r = w*2 + rr;
            if (r < tk) {
                int key = __ldg(&lst[base + r]);
                const float4* src = (const float4*)g_kv + key*144;
                float4* dst = kvs + r*144;
                dst[lane]      = src[lane];
                dst[lane + 32] = src[lane + 32];
                dst[lane + 64] = src[lane + 64];
                dst[lane + 96] = src[lane + 96];
                if (half) dst[128 + lane] = src[128 + lane];
            }
        }
        __syncthreads();
        for (int j = 0; j < tk; j++) {
            const u64* kr = (const u64*)(kvs + j*144);
            u64 b[8];
#pragma unroll
            for (int u = 0; u < 4; u++) {
                b[2*u]   = kr[(lane+32*u)*2];
                b[2*u+1] = kr[(lane+32*u)*2 + 1];
            }
            u64 sa2 = 0ULL, sb2 = 0ULL;
#pragma unroll
            for (int p = 0; p < 8; p++) {
                sa2 = fma2(qa[p], b[p], sa2);
                sb2 = fma2(qb[p], b[p], sb2);
            }
            if (half) {
                u64 bt0 = kr[(128+lane)*2], bt1 = kr[(128+lane)*2 + 1];
                sa2 = fma2(qa[8], bt0, sa2); sa2 = fma2(qa[9], bt1, sa2);
                sb2 = fma2(qb[8], bt0, sb2); sb2 = fma2(qb[9], bt1, sb2);
            }
            float sA = hsum2(sa2), sB = hsum2(sb2);
#pragma unroll
            for (int o = 16; o; o >>= 1) {
                sA += __shfl_xor_sync(0xffffffffu, sA, o);
                sB += __shfl_xor_sync(0xffffffffu, sB, o);
            }
            float lg0 = sA * SCALE, lg1 = sB * SCALE;
            if (lg0 > m0) {
                float c = __expf(m0 - lg0); l0 *= c;
                u64 c2 = pkdup(c);
#pragma unroll
                for (int p = 0; p < 8; p++) o0[p] = mul2(o0[p], c2);
                m0 = lg0;
            }
            float p0 = __expf(lg0 - m0); l0 += p0;
            u64 p02 = pkdup(p0);
#pragma unroll
            for (int p = 0; p < 8; p++) o0[p] = fma2(p02, b[p], o0[p]);
            if (lg1 > m1) {
                float c = __expf(m1 - lg1); l1 *= c;
                u64 c2 = pkdup(c);
#pragma unroll
                for (int p = 0; p < 8; p++) o1[p] = mul2(o1[p], c2);
                m1 = lg1;
            }
            float p1 = __expf(lg1 - m1); l1 += p1;
            u64 p12 = pkdup(p1);
#pragma unroll
            for (int p = 0; p < 8; p++) o1[p] = fma2(p12, b[p], o1[p]);
        }
        __syncthreads();
    }
    u64 i02 = pkdup(1.f/l0), i12 = pkdup(1.f/l1);
    float4* ao = (float4*)g_attn + (long long)qi * (NH*DV/4);
#pragma unroll
    for (int u = 0; u < 4; u++) {
        float4 v, v2;
        u64 r0 = mul2(o0[2*u], i02), r1 = mul2(o0[2*u+1], i02);
        upk(r0, v.x, v.y); upk(r1, v.z, v.w);
        ao[h0*128 + lane + 32*u] = v;
        u64 s0 = mul2(o1[2*u], i12), s1 = mul2(o1[2*u+1], i12);
        upk(s0, v2.x, v2.y); upk(s1, v2.z, v2.w);
        ao[h1*128 + lane + 32*u] = v2;
    }
}

template <typename T> static T* sym(const void* s) {
    void* p = nullptr; cudaGetSymbolAddress(&p, s); return (T*)p;
}

extern "C" void kernel_launch(void* const* d_in, const int* in_sizes, int n_in,
                              void* d_out, int out_size)
{
    (void)in_sizes; (void)n_in; (void)out_size;
    const float* q_latent = (const float*)d_in[0];
    const float* hidden   = (const float*)d_in[1];
    const float* cosb     = (const float*)d_in[2];
    const float* sinb     = (const float*)d_in[3];
    const float* q_pass   = (const float*)d_in[4];
    const float* q_rot    = (const float*)d_in[5];
    const float* k_pass   = (const float*)d_in[6];
    const float* k_rot    = (const float*)d_in[7];
    const float* kvb      = (const float*)d_in[9];
    const float* wqb      = (const float*)d_in[10];
    const float* wkw      = (const float*)d_in[11];
    const float* knorm    = (const float*)d_in[12];
    const float* wpw      = (const float*)d_in[13];
    const float* wpb      = (const float*)d_in[14];
    float* out = (float*)d_out;

    float* p_q     = sym<float>(g_q);
    float* p_ql    = sym<float>(g_ql);
    float* p_part  = sym<float>(g_part);
    float* p_partw = sym<float>(g_partw);
    float* p_attn  = sym<float>(g_attn);

    // ql = q_latent @ wq_b^T   (2048x2048, K=1536)
    sgemm_nt<<<dim3(16,16,1), 256>>>(q_latent, wqb, p_ql, 2048, 1536,
                                     1536, 1536, 2048, 0, 0, 0, 0);
    // ckv = hidden @ wk^T (split-K over 8 chunks of 256)
    sgemm_nt<<<dim3(1,16,8), 256>>>(hidden, wkw, p_part, 128, 256,
                                    2048, 2048, 128, 256, 256, (long long)SEQ*128, 0);
    // w partials = hidden @ wproj^T (split-K)
    sgemm_nt<<<dim3(1,16,8), 256>>>(hidden, wpw, p_partw, 16, 256,
                                    2048, 2048, 16, 256, 256, (long long)SEQ*16, 0);
    reduce_ckv<<<1024, 256>>>();
    reduce_w  <<<128, 256>>>(wpb);
    // q_abs[h]: q_pass[h] @ k_b[h]^T (NN via transB, no explicit transpose)
    sgemm_nt<<<dim3(4,16,16), 256>>>(q_pass, kvb, p_q, 512, 128,
                                     128, 512, NH*DQK,
                                     (long long)SEQ*128, 256LL*512, DQK, 1);
    build_kv  <<<4608, 256>>>(k_pass, k_rot);
    build_qrot<<<8192, 256>>>(q_rot);
    build_ik  <<<SEQ, 64>>>(cosb, sinb, knorm);
    rope_iq   <<<4096, 256>>>(cosb, sinb);

    indexer_kernel<<<SEQ, 256>>>();
    attn_kernel<<<SEQ, 256>>>();

    // out[s,h,d] = sum_r attn[s,h,r] * v_b[h,d,r]
    sgemm_nt<<<dim3(1,16,16), 256>>>(p_attn, kvb + 128*512, out, 128, 512,
                                     NH*DV, 512, NH*128,
                                     512LL, 256LL*512, 128LL, 0);
}